// round 14
// baseline (speedup 1.0000x reference)
#include <cuda_runtime.h>
#include <stdint.h>

// Problem constants (fixed by the reference)
#define NXD   432
#define NYD   496
#define BD    4
#define CD    64
#define PLANE (NXD * NYD)        // 214272 = 837 * 256 (exact)
#define NBINS 3
#define NPIL  64000              // p+1 <= 64000 -> fits uint16
#define NBB   (NBINS * BD)       // 12 (bin,b) canvases

// Pillar-index canvas. Encoding: 0 = empty, p+1 = pillar index p.
// Zero-initialized at module load; the gather kernel restores every entry
// to 0 after reading it, so the canvas is all-"empty" at the start of every
// kernel_launch call. No init kernel needed.
__device__ unsigned short g_idx[NBB * PLANE];   // 5.1 MB, L2-resident

// ---------------------------------------------------------------------------
// Kernel 1: scatter pillar indices (p+1) into the canvas.
// coords row layout: [b, z, y, x]; local = z + y*NX + x  (nz == 1)
// ---------------------------------------------------------------------------
__global__ void scatter_idx_kernel(const int* __restrict__ c0,
                                   const int* __restrict__ c1,
                                   const int* __restrict__ c2) {
    int t = blockIdx.x * blockDim.x + threadIdx.x;
    if (t >= NBINS * NPIL) return;
    int bin = t / NPIL;
    int p   = t - bin * NPIL;
    const int* cbase = (bin == 0) ? c0 : (bin == 1) ? c1 : c2;
    int4 cr = reinterpret_cast<const int4*>(cbase)[p];   // [b, z, y, x]
    int local = cr.y + cr.z * NXD + cr.w;
    g_idx[(bin * BD + cr.x) * PLANE + local] = (unsigned short)(p + 1);
}

// ---------------------------------------------------------------------------
// Kernel 2: gather, R11 structure (16-channel chunks, 1 pos/thread, the
// 112.7us shape). ONLY change vs R11: pillar loads are per-lane PREDICATED
// (@occ) instead of clamped-broadcast -- empty lanes (92%) issue no memory
// transactions at all, cutting L1 load wavefronts; registers are pre-zeroed
// so all 64 stores remain unconditional, SEL-free, warp-coalesced STG.32.
// ---------------------------------------------------------------------------
__global__ void __launch_bounds__(256)
gather_kernel(const float* __restrict__ p0,
              const float* __restrict__ p1,
              const float* __restrict__ p2,
              float* __restrict__ out) {
    int pos = blockIdx.x * 256 + threadIdx.x;  // 0..PLANE-1 (exact cover)
    int bb  = blockIdx.y;                      // 0..11 = bin*4 + b
    int bin = bb >> 2;
    const float* pil = (bin == 0) ? p0 : (bin == 1) ? p1 : p2;

    unsigned short* ip = g_idx + (size_t)bb * PLANE + pos;
    unsigned int idx = *ip;
    *ip = 0;                                   // restore empty state
    bool occ = idx != 0u;

    const float4* row =
        reinterpret_cast<const float4*>(pil) + (size_t)(idx - 1u) * (CD / 4);
    float* o = out + (size_t)bb * CD * PLANE + pos;

#pragma unroll
    for (int ch = 0; ch < 4; ch++) {           // 4 chunks of 16 channels
        float4 r[4];
#pragma unroll
        for (int q = 0; q < 4; q++) r[q] = make_float4(0.f, 0.f, 0.f, 0.f);
        if (occ) {
#pragma unroll
            for (int q = 0; q < 4; q++) r[q] = __ldg(row + ch * 4 + q);
        }
#pragma unroll
        for (int q = 0; q < 4; q++) {
            int c = ch * 16 + q * 4;
            o[(size_t)(c + 0) * PLANE] = r[q].x;
            o[(size_t)(c + 1) * PLANE] = r[q].y;
            o[(size_t)(c + 2) * PLANE] = r[q].z;
            o[(size_t)(c + 3) * PLANE] = r[q].w;
        }
    }
}

// ---------------------------------------------------------------------------
// Launch. Input order (metadata): pf0, vc0, pf1, vc1, pf2, vc2.
// Output: 3 canvases [4,64,496,432] f32 concatenated.
// ---------------------------------------------------------------------------
extern "C" void kernel_launch(void* const* d_in, const int* in_sizes, int n_in,
                              void* d_out, int out_size) {
    const float* pf0 = (const float*)d_in[0];
    const int*   vc0 = (const int*)  d_in[1];
    const float* pf1 = (const float*)d_in[2];
    const int*   vc1 = (const int*)  d_in[3];
    const float* pf2 = (const float*)d_in[4];
    const int*   vc2 = (const int*)  d_in[5];
    float* out = (float*)d_out;

    // 1) scatter pillar indices into the (all-empty) canvas
    {
        int n = NBINS * NPIL;
        scatter_idx_kernel<<<(n + 255) / 256, 256>>>(vc0, vc1, vc2);
    }
    // 2) gather -> dense output; self-clears the canvas
    {
        dim3 blocks(PLANE / 256, NBB);   // (837, 12), exact cover
        gather_kernel<<<blocks, 256>>>(pf0, pf1, pf2, out);
    }
}

// round 16
// speedup vs baseline: 1.8740x; 1.8740x over previous
#include <cuda_runtime.h>
#include <stdint.h>

// Problem constants (fixed by the reference)
#define NXD   432
#define NYD   496
#define BD    4
#define CD    64
#define PLANE (NXD * NYD)        // 214272 = 837 * 256 (exact)
#define NBINS 3
#define NPIL  64000              // < 65535 -> fits uint16
#define NBB   (NBINS * BD)       // 12 (bin,b) canvases

// Scratch: pillar-index canvas, 0xFFFF = empty. 5.1 MB, L2-resident.
__device__ unsigned short g_idx[NBB * PLANE];

// ---------------------------------------------------------------------------
// Kernel 1: fill index canvas with 0xFFFF (int4 = 8 u16 per store)
// ---------------------------------------------------------------------------
__global__ void init_idx_kernel() {
    const int n8 = (NBB * PLANE) / 8;   // 321408
    int t = blockIdx.x * blockDim.x + threadIdx.x;
    if (t < n8) {
        reinterpret_cast<int4*>(g_idx)[t] = make_int4(-1, -1, -1, -1);
    }
}

// ---------------------------------------------------------------------------
// Kernel 2: scatter pillar indices into the canvas.
// coords row layout: [b, z, y, x]; local = z + y*NX + x  (nz == 1)
// ---------------------------------------------------------------------------
__global__ void scatter_idx_kernel(const int* __restrict__ c0,
                                   const int* __restrict__ c1,
                                   const int* __restrict__ c2) {
    int t = blockIdx.x * blockDim.x + threadIdx.x;
    if (t >= NBINS * NPIL) return;
    int bin = t / NPIL;
    int p   = t - bin * NPIL;
    const int* cbase = (bin == 0) ? c0 : (bin == 1) ? c1 : c2;
    int4 cr = reinterpret_cast<const int4*>(cbase)[p];   // [b, z, y, x]
    int local = cr.y + cr.z * NXD + cr.w;
    g_idx[(bin * BD + cr.x) * PLANE + local] = (unsigned short)p;
}

// ---------------------------------------------------------------------------
// Kernel 3: gather — the proven R11 inner chunk (16 channels, clamped
// broadcast loads, SEL stores), but each block handles ONE chunk selected by
// blockIdx.z. Blocks schedule x->y->z, so at any instant only ~16 channel
// planes are being written chip-wide (vs 64), cutting concurrent DRAM row
// streams 4x. idx is re-read by 4 blocks (L2-resident, cheap).
// ---------------------------------------------------------------------------
__global__ void __launch_bounds__(256)
gather_kernel(const float* __restrict__ p0,
              const float* __restrict__ p1,
              const float* __restrict__ p2,
              float* __restrict__ out) {
    int pos = blockIdx.x * 256 + threadIdx.x;  // 0..PLANE-1 (exact cover)
    int bb  = blockIdx.y;                      // 0..11 = bin*4 + b
    int ch  = blockIdx.z;                      // 0..3 = 16-channel group
    int bin = bb >> 2;
    const float* pil = (bin == 0) ? p0 : (bin == 1) ? p1 : p2;

    unsigned int idx = __ldg(g_idx + (size_t)bb * PLANE + pos);
    bool occ = idx != 0xFFFFu;
    const float4* row =
        reinterpret_cast<const float4*>(pil) + (size_t)(occ ? idx : 0u) * (CD / 4);
    float* o = out + (size_t)bb * CD * PLANE + pos;

    float4 r[4];
#pragma unroll
    for (int q = 0; q < 4; q++) r[q] = __ldg(row + ch * 4 + q);
#pragma unroll
    for (int q = 0; q < 4; q++) {
        int c = ch * 16 + q * 4;
        o[(size_t)(c + 0) * PLANE] = occ ? r[q].x : 0.f;
        o[(size_t)(c + 1) * PLANE] = occ ? r[q].y : 0.f;
        o[(size_t)(c + 2) * PLANE] = occ ? r[q].z : 0.f;
        o[(size_t)(c + 3) * PLANE] = occ ? r[q].w : 0.f;
    }
}

// ---------------------------------------------------------------------------
// Launch. Input order (metadata): pf0, vc0, pf1, vc1, pf2, vc2.
// Output: 3 canvases [4,64,496,432] f32 concatenated.
// ---------------------------------------------------------------------------
extern "C" void kernel_launch(void* const* d_in, const int* in_sizes, int n_in,
                              void* d_out, int out_size) {
    const float* pf0 = (const float*)d_in[0];
    const int*   vc0 = (const int*)  d_in[1];
    const float* pf1 = (const float*)d_in[2];
    const int*   vc1 = (const int*)  d_in[3];
    const float* pf2 = (const float*)d_in[4];
    const int*   vc2 = (const int*)  d_in[5];
    float* out = (float*)d_out;

    // 1) reset index canvas (5.1 MB of 0xFFFF, L2-resident)
    {
        int n8 = (NBB * PLANE) / 8;
        init_idx_kernel<<<(n8 + 255) / 256, 256>>>();
    }
    // 2) scatter pillar indices (tiny)
    {
        int n = NBINS * NPIL;
        scatter_idx_kernel<<<(n + 255) / 256, 256>>>(vc0, vc1, vc2);
    }
    // 3) gather -> dense output, channel-split across gridDim.z
    {
        dim3 blocks(PLANE / 256, NBB, 4);   // (837, 12, 4), exact cover
        gather_kernel<<<blocks, 256>>>(pf0, pf1, pf2, out);
    }
}

// round 17
// speedup vs baseline: 1.9703x; 1.0514x over previous
#include <cuda_runtime.h>
#include <stdint.h>

// Problem constants (fixed by the reference)
#define NXD   432
#define NYD   496
#define BD    4
#define CD    64
#define PLANE (NXD * NYD)        // 214272 = 837 * 256 (exact)
#define NBINS 3
#define NPIL  64000              // < 65535 -> fits uint16
#define NBB   (NBINS * BD)       // 12 (bin,b) canvases

// Scratch: pillar-index canvas, 0xFFFF = empty. 5.1 MB, L2-resident.
__device__ unsigned short g_idx[NBB * PLANE];

// ---------------------------------------------------------------------------
// Kernel 1: fill index canvas with 0xFFFF (int4 = 8 u16 per store)
// ---------------------------------------------------------------------------
__global__ void init_idx_kernel() {
    const int n8 = (NBB * PLANE) / 8;   // 321408
    int t = blockIdx.x * blockDim.x + threadIdx.x;
    if (t < n8) {
        reinterpret_cast<int4*>(g_idx)[t] = make_int4(-1, -1, -1, -1);
    }
}

// ---------------------------------------------------------------------------
// Kernel 2: scatter pillar indices into the canvas.
// coords row layout: [b, z, y, x]; local = z + y*NX + x  (nz == 1)
// ---------------------------------------------------------------------------
__global__ void scatter_idx_kernel(const int* __restrict__ c0,
                                   const int* __restrict__ c1,
                                   const int* __restrict__ c2) {
    int t = blockIdx.x * blockDim.x + threadIdx.x;
    if (t >= NBINS * NPIL) return;
    int bin = t / NPIL;
    int p   = t - bin * NPIL;
    const int* cbase = (bin == 0) ? c0 : (bin == 1) ? c1 : c2;
    int4 cr = reinterpret_cast<const int4*>(cbase)[p];   // [b, z, y, x]
    int local = cr.y + cr.z * NXD + cr.w;
    g_idx[(bin * BD + cr.x) * PLANE + local] = (unsigned short)p;
}

// ---------------------------------------------------------------------------
// Kernel 3: branch-free gather — EXACT R8 champion structure (119.5us):
// one thread per BEV position, 4 chunks of 16 channels, clamped broadcast
// loads, SEL stores, 256-thread blocks. ONLY change: output stores are
// __stcs (evict-first) so the 659MB write stream doesn't flush the 49MB
// pillar working set out of L2 between graph replays.
// ---------------------------------------------------------------------------
__global__ void __launch_bounds__(256)
gather_kernel(const float* __restrict__ p0,
              const float* __restrict__ p1,
              const float* __restrict__ p2,
              float* __restrict__ out) {
    int pos = blockIdx.x * 256 + threadIdx.x;  // 0..PLANE-1 (exact cover)
    int bb  = blockIdx.y;                      // 0..11 = bin*4 + b
    int bin = bb >> 2;
    const float* pil = (bin == 0) ? p0 : (bin == 1) ? p1 : p2;

    unsigned int idx = __ldg(g_idx + (size_t)bb * PLANE + pos);
    bool occ = idx != 0xFFFFu;
    const float4* row =
        reinterpret_cast<const float4*>(pil) + (size_t)(occ ? idx : 0u) * (CD / 4);
    float* o = out + (size_t)bb * CD * PLANE + pos;

#pragma unroll
    for (int ch = 0; ch < 4; ch++) {           // 4 chunks of 16 channels
        float4 r[4];
#pragma unroll
        for (int q = 0; q < 4; q++) r[q] = __ldg(row + ch * 4 + q);
#pragma unroll
        for (int q = 0; q < 4; q++) {
            int c = ch * 16 + q * 4;
            __stcs(o + (size_t)(c + 0) * PLANE, occ ? r[q].x : 0.f);
            __stcs(o + (size_t)(c + 1) * PLANE, occ ? r[q].y : 0.f);
            __stcs(o + (size_t)(c + 2) * PLANE, occ ? r[q].z : 0.f);
            __stcs(o + (size_t)(c + 3) * PLANE, occ ? r[q].w : 0.f);
        }
    }
}

// ---------------------------------------------------------------------------
// Launch. Input order (metadata): pf0, vc0, pf1, vc1, pf2, vc2.
// Output: 3 canvases [4,64,496,432] f32 concatenated.
// ---------------------------------------------------------------------------
extern "C" void kernel_launch(void* const* d_in, const int* in_sizes, int n_in,
                              void* d_out, int out_size) {
    const float* pf0 = (const float*)d_in[0];
    const int*   vc0 = (const int*)  d_in[1];
    const float* pf1 = (const float*)d_in[2];
    const int*   vc1 = (const int*)  d_in[3];
    const float* pf2 = (const float*)d_in[4];
    const int*   vc2 = (const int*)  d_in[5];
    float* out = (float*)d_out;

    // 1) reset index canvas (5.1 MB of 0xFFFF, L2-resident)
    {
        int n8 = (NBB * PLANE) / 8;
        init_idx_kernel<<<(n8 + 255) / 256, 256>>>();
    }
    // 2) scatter pillar indices (tiny)
    {
        int n = NBINS * NPIL;
        scatter_idx_kernel<<<(n + 255) / 256, 256>>>(vc0, vc1, vc2);
    }
    // 3) branch-free gather -> dense output (streaming-store bound)
    {
        dim3 blocks(PLANE / 256, NBB);   // (837, 12), exact cover
        gather_kernel<<<blocks, 256>>>(pf0, pf1, pf2, out);
    }
}